// round 1
// baseline (speedup 1.0000x reference)
#include <cuda_runtime.h>
#include <cuda_bf16.h>
#include <math.h>

// Problem constants
#define BATCH 2
#define SEQ   2048
#define CDIM  2048
#define NHEAD 16
#define NKV   4
#define HDIM  128
#define HALF  64
#define MROWS (BATCH*SEQ)          // 4096
#define QW    (NHEAD*HDIM)         // 2048
#define KW    (NKV*HDIM)           // 512

// Scratch (device globals; no allocations allowed)
__device__ float g_q[MROWS * QW];     // 32 MB
__device__ float g_k[MROWS * KW];     // 8 MB
__device__ float g_v[MROWS * KW];     // 8 MB
__device__ float g_att[MROWS * QW];   // 32 MB

// ---------------------------------------------------------------------------
// SGEMM: C[M,N] = A[M,K] @ B[K,N] (+bias). Row-major. M,N,K multiples of 128/8.
// 128x128 block, BK=8, 256 threads, 8x8 per-thread microtile.
// ---------------------------------------------------------------------------
#define GBM 128
#define GBN 128
#define GBK 8

__global__ __launch_bounds__(256, 2)
void sgemm_kernel(const float* __restrict__ A, const float* __restrict__ B,
                  float* __restrict__ C, int M, int N, int K,
                  const float* __restrict__ bias)
{
    __shared__ float As[GBK][132];   // transposed, padded
    __shared__ float Bs[GBK][128];

    const int tid  = threadIdx.x;
    const int m0   = blockIdx.y * GBM;
    const int n0   = blockIdx.x * GBN;
    const int trow = tid >> 4;       // 0..15
    const int tcol = tid & 15;       // 0..15

    const int a_r  = tid >> 1;       // 0..127
    const int a_c4 = tid & 1;        // 0..1
    const int b_r  = tid >> 5;       // 0..7
    const int b_c4 = tid & 31;       // 0..31

    float acc[8][8];
#pragma unroll
    for (int i = 0; i < 8; i++)
#pragma unroll
        for (int j = 0; j < 8; j++) acc[i][j] = 0.f;

    const float* Ap = A + (size_t)(m0 + a_r) * K + a_c4 * 4;
    const float* Bp = B + (size_t)b_r * N + n0 + b_c4 * 4;

    for (int k0 = 0; k0 < K; k0 += GBK) {
        float4 av = *reinterpret_cast<const float4*>(Ap + k0);
        float4 bv = *reinterpret_cast<const float4*>(Bp + (size_t)k0 * N);
        As[a_c4 * 4 + 0][a_r] = av.x;
        As[a_c4 * 4 + 1][a_r] = av.y;
        As[a_c4 * 4 + 2][a_r] = av.z;
        As[a_c4 * 4 + 3][a_r] = av.w;
        *reinterpret_cast<float4*>(&Bs[b_r][b_c4 * 4]) = bv;
        __syncthreads();

#pragma unroll
        for (int kk = 0; kk < GBK; ++kk) {
            float4 a0 = *reinterpret_cast<const float4*>(&As[kk][trow * 8]);
            float4 a1 = *reinterpret_cast<const float4*>(&As[kk][trow * 8 + 4]);
            float4 b0 = *reinterpret_cast<const float4*>(&Bs[kk][tcol * 8]);
            float4 b1 = *reinterpret_cast<const float4*>(&Bs[kk][tcol * 8 + 4]);
            float am[8] = {a0.x, a0.y, a0.z, a0.w, a1.x, a1.y, a1.z, a1.w};
            float bn[8] = {b0.x, b0.y, b0.z, b0.w, b1.x, b1.y, b1.z, b1.w};
#pragma unroll
            for (int i = 0; i < 8; i++)
#pragma unroll
                for (int j = 0; j < 8; j++)
                    acc[i][j] += am[i] * bn[j];
        }
        __syncthreads();
    }

#pragma unroll
    for (int i = 0; i < 8; i++) {
        int row = m0 + trow * 8 + i;
        float* Cp = C + (size_t)row * N + n0 + tcol * 8;
        float4 r0, r1;
        if (bias != nullptr) {
            const float* bp = bias + n0 + tcol * 8;
            r0.x = acc[i][0] + bp[0]; r0.y = acc[i][1] + bp[1];
            r0.z = acc[i][2] + bp[2]; r0.w = acc[i][3] + bp[3];
            r1.x = acc[i][4] + bp[4]; r1.y = acc[i][5] + bp[5];
            r1.z = acc[i][6] + bp[6]; r1.w = acc[i][7] + bp[7];
        } else {
            r0.x = acc[i][0]; r0.y = acc[i][1]; r0.z = acc[i][2]; r0.w = acc[i][3];
            r1.x = acc[i][4]; r1.y = acc[i][5]; r1.z = acc[i][6]; r1.w = acc[i][7];
        }
        *reinterpret_cast<float4*>(Cp)     = r0;
        *reinterpret_cast<float4*>(Cp + 4) = r1;
    }
}

// ---------------------------------------------------------------------------
// RMSNorm + RoPE, in-place on q (B*T*NHEAD rows) and k (B*T*NKV rows).
// One 128-thread block per head-row.
// ---------------------------------------------------------------------------
__global__ void norm_rope_kernel(float* __restrict__ q, float* __restrict__ k,
                                 const float* __restrict__ cosp,
                                 const float* __restrict__ sinp)
{
    const long bid = blockIdx.x;
    const int  d   = threadIdx.x;   // 0..127
    float* row;
    int t;
    if (bid < (long)MROWS * NHEAD) {
        int bt = (int)(bid / NHEAD);
        int h  = (int)(bid % NHEAD);
        t = bt % SEQ;
        row = q + (size_t)bt * QW + h * HDIM;
    } else {
        long r = bid - (long)MROWS * NHEAD;
        int bt = (int)(r / NKV);
        int h  = (int)(r % NKV);
        t = bt % SEQ;
        row = k + (size_t)bt * KW + h * HDIM;
    }

    float val = row[d];
    float ss  = val * val;
#pragma unroll
    for (int off = 16; off; off >>= 1)
        ss += __shfl_xor_sync(0xffffffffu, ss, off);

    __shared__ float red[4];
    if ((d & 31) == 0) red[d >> 5] = ss;
    __syncthreads();
    float total = red[0] + red[1] + red[2] + red[3];
    float rms = rsqrtf(total * (1.0f / 128.0f) + 1.1920929e-7f);
    val *= rms;

    __shared__ float sh[128];
    sh[d] = val;
    __syncthreads();

    float out;
    if (d < HALF) {
        float c = cosp[t * HALF + d], s = sinp[t * HALF + d];
        out = val * c - sh[d + HALF] * s;
    } else {
        int f = d - HALF;
        float c = cosp[t * HALF + f], s = sinp[t * HALF + f];
        out = sh[f] * s + val * c;
    }
    row[d] = out;
}

// ---------------------------------------------------------------------------
// Flash attention, causal, GQA. 64x64 tiles, D=128, fp32 online softmax.
// 256 threads as 16x16: each thread 4x4 scores (cols tx+16j), 4x8 O accum.
// ---------------------------------------------------------------------------
#define FBM 64
#define FBN 64
#define QPITCH 132
#define SPITCH 68
#define ATTN_SMEM ((3 * FBM * QPITCH + FBM * SPITCH + 3 * FBM) * 4)

__global__ __launch_bounds__(256)
void flash_attn_kernel(const float* __restrict__ q, const float* __restrict__ k,
                       const float* __restrict__ v, float* __restrict__ att)
{
    extern __shared__ float sm[];
    float* Qs   = sm;                        // 64 x 132
    float* Ks   = Qs + FBM * QPITCH;         // 64 x 132
    float* Vs   = Ks + FBM * QPITCH;         // 64 x 132
    float* Ss   = Vs + FBM * QPITCH;         // 64 x 68
    float* mrow = Ss + FBM * SPITCH;         // 64
    float* lrow = mrow + FBM;                // 64
    float* arow = lrow + FBM;                // 64

    const int qt  = blockIdx.x;              // q tile: 0..31
    const int bh  = blockIdx.y;              // 0..31
    const int b   = bh >> 4;
    const int h   = bh & 15;
    const int hkv = h >> 2;
    const int tid = threadIdx.x;
    const int ty  = tid >> 4;                // 0..15
    const int tx  = tid & 15;                // 0..15
    const int q0  = qt * FBM;
    const float scale = 0.08838834764831845f;   // 1/sqrt(128)

    const float* qbase = q + (size_t)b * SEQ * QW + h   * HDIM;
    const float* kbase = k + (size_t)b * SEQ * KW + hkv * HDIM;
    const float* vbase = v + (size_t)b * SEQ * KW + hkv * HDIM;

    // load Q tile (coalesced float4)
    for (int i = tid; i < FBM * 32; i += 256) {
        int r = i >> 5, c4 = i & 31;
        *reinterpret_cast<float4*>(&Qs[r * QPITCH + c4 * 4]) =
            *reinterpret_cast<const float4*>(qbase + (size_t)(q0 + r) * QW + c4 * 4);
    }
    if (tid < FBM) { mrow[tid] = -1e30f; lrow[tid] = 0.f; }

    float o[4][8];
#pragma unroll
    for (int i = 0; i < 4; i++)
#pragma unroll
        for (int j = 0; j < 8; j++) o[i][j] = 0.f;

    const int ntiles = qt + 1;
    for (int kt = 0; kt < ntiles; ++kt) {
        const int k0 = kt * FBN;
        __syncthreads();   // protect Ks/Vs/Ss from previous iteration readers
        for (int i = tid; i < FBN * 32; i += 256) {
            int r = i >> 5, c4 = i & 31;
            *reinterpret_cast<float4*>(&Ks[r * QPITCH + c4 * 4]) =
                *reinterpret_cast<const float4*>(kbase + (size_t)(k0 + r) * KW + c4 * 4);
            *reinterpret_cast<float4*>(&Vs[r * QPITCH + c4 * 4]) =
                *reinterpret_cast<const float4*>(vbase + (size_t)(k0 + r) * KW + c4 * 4);
        }
        __syncthreads();

        // S = Q K^T  (4x4 per thread; cols tx + 16j)
        float s[4][4];
#pragma unroll
        for (int i = 0; i < 4; i++)
#pragma unroll
            for (int j = 0; j < 4; j++) s[i][j] = 0.f;

        for (int dd = 0; dd < HDIM; dd += 4) {
            float4 qv[4], kv[4];
#pragma unroll
            for (int i = 0; i < 4; i++)
                qv[i] = *reinterpret_cast<const float4*>(&Qs[(ty * 4 + i) * QPITCH + dd]);
#pragma unroll
            for (int j = 0; j < 4; j++)
                kv[j] = *reinterpret_cast<const float4*>(&Ks[(tx + 16 * j) * QPITCH + dd]);
#pragma unroll
            for (int i = 0; i < 4; i++)
#pragma unroll
                for (int j = 0; j < 4; j++) {
                    s[i][j] += qv[i].x * kv[j].x;
                    s[i][j] += qv[i].y * kv[j].y;
                    s[i][j] += qv[i].z * kv[j].z;
                    s[i][j] += qv[i].w * kv[j].w;
                }
        }

        const bool diag = (kt == qt);
#pragma unroll
        for (int i = 0; i < 4; i++) {
            int r = ty * 4 + i;
#pragma unroll
            for (int j = 0; j < 4; j++) {
                int c = tx + 16 * j;
                float val = s[i][j] * scale;
                if (diag && (k0 + c > q0 + r)) val = -1e30f;
                s[i][j] = val;
                Ss[r * SPITCH + c] = val;
            }
        }
        __syncthreads();

        // per-row max + rescale factor
        if (tid < FBM) {
            float mx = -1e30f;
            const float* srow = &Ss[tid * SPITCH];
            for (int c = 0; c < FBN; c++) mx = fmaxf(mx, srow[c]);
            float m_new = fmaxf(mrow[tid], mx);
            arow[tid] = __expf(mrow[tid] - m_new);
            mrow[tid] = m_new;
        }
        __syncthreads();

        // P = exp(S - m); rescale O accumulators
#pragma unroll
        for (int i = 0; i < 4; i++) {
            int r = ty * 4 + i;
            float mn = mrow[r];
#pragma unroll
            for (int j = 0; j < 4; j++)
                Ss[r * SPITCH + tx + 16 * j] = __expf(s[i][j] - mn);
        }
#pragma unroll
        for (int i = 0; i < 4; i++) {
            float a = arow[ty * 4 + i];
#pragma unroll
            for (int j = 0; j < 8; j++) o[i][j] *= a;
        }
        __syncthreads();

        // row sums
        if (tid < FBM) {
            float sum = 0.f;
            const float* srow = &Ss[tid * SPITCH];
            for (int c = 0; c < FBN; c++) sum += srow[c];
            lrow[tid] = arow[tid] * lrow[tid] + sum;
        }

        // O += P V  (cols tx*8 + j)
        for (int c = 0; c < FBN; c++) {
            float pv[4];
#pragma unroll
            for (int i = 0; i < 4; i++) pv[i] = Ss[(ty * 4 + i) * SPITCH + c];
            float4 v0 = *reinterpret_cast<const float4*>(&Vs[c * QPITCH + tx * 8]);
            float4 v1 = *reinterpret_cast<const float4*>(&Vs[c * QPITCH + tx * 8 + 4]);
#pragma unroll
            for (int i = 0; i < 4; i++) {
                o[i][0] += pv[i] * v0.x; o[i][1] += pv[i] * v0.y;
                o[i][2] += pv[i] * v0.z; o[i][3] += pv[i] * v0.w;
                o[i][4] += pv[i] * v1.x; o[i][5] += pv[i] * v1.y;
                o[i][6] += pv[i] * v1.z; o[i][7] += pv[i] * v1.w;
            }
        }
    }
    __syncthreads();   // ensure final lrow writes are visible

#pragma unroll
    for (int i = 0; i < 4; i++) {
        int r = ty * 4 + i;
        float inv = 1.0f / lrow[r];
        float* op = att + (size_t)(b * SEQ + q0 + r) * QW + h * HDIM + tx * 8;
        float4 r0, r1;
        r0.x = o[i][0] * inv; r0.y = o[i][1] * inv;
        r0.z = o[i][2] * inv; r0.w = o[i][3] * inv;
        r1.x = o[i][4] * inv; r1.y = o[i][5] * inv;
        r1.z = o[i][6] * inv; r1.w = o[i][7] * inv;
        *reinterpret_cast<float4*>(op)     = r0;
        *reinterpret_cast<float4*>(op + 4) = r1;
    }
}

// ---------------------------------------------------------------------------
// Launch
// ---------------------------------------------------------------------------
extern "C" void kernel_launch(void* const* d_in, const int* in_sizes, int n_in,
                              void* d_out, int out_size)
{
    const float* x    = (const float*)d_in[0];
    const float* cosp = (const float*)d_in[1];
    const float* sinp = (const float*)d_in[2];
    const float* Wq   = (const float*)d_in[3];
    const float* Wk   = (const float*)d_in[4];
    const float* Wv   = (const float*)d_in[5];
    const float* Wo   = (const float*)d_in[6];
    const float* bo   = (const float*)d_in[7];
    float* out = (float*)d_out;

    float *qs, *ks, *vs, *att;
    cudaGetSymbolAddress((void**)&qs,  g_q);
    cudaGetSymbolAddress((void**)&ks,  g_k);
    cudaGetSymbolAddress((void**)&vs,  g_v);
    cudaGetSymbolAddress((void**)&att, g_att);

    // QKV projections
    dim3 gq(QW / GBN, MROWS / GBM);   // (16, 32)
    dim3 gk(KW / GBN, MROWS / GBM);   // (4, 32)
    sgemm_kernel<<<gq, 256>>>(x, Wq, qs, MROWS, QW, CDIM, nullptr);
    sgemm_kernel<<<gk, 256>>>(x, Wk, ks, MROWS, KW, CDIM, nullptr);
    sgemm_kernel<<<gk, 256>>>(x, Wv, vs, MROWS, KW, CDIM, nullptr);

    // RMSNorm + RoPE (in place)
    norm_rope_kernel<<<MROWS * (NHEAD + NKV), 128>>>(qs, ks, cosp, sinp);

    // Flash attention
    cudaFuncSetAttribute(flash_attn_kernel,
                         cudaFuncAttributeMaxDynamicSharedMemorySize, ATTN_SMEM);
    dim3 ga(SEQ / FBM, BATCH * NHEAD);  // (32, 32)
    flash_attn_kernel<<<ga, 256, ATTN_SMEM>>>(qs, ks, vs, att);

    // Output projection + bias
    sgemm_kernel<<<gq, 256>>>(att, Wo, out, MROWS, QW, CDIM, bo);
}

// round 3
// speedup vs baseline: 1.7400x; 1.7400x over previous
#include <cuda_runtime.h>
#include <cuda_bf16.h>
#include <math.h>
#include <stdint.h>

// Problem constants
#define BATCH 2
#define SEQ   2048
#define CDIM  2048
#define NHEAD 16
#define NKV   4
#define HDIM  128
#define HALF  64
#define MROWS (BATCH*SEQ)          // 4096
#define QW    (NHEAD*HDIM)         // 2048
#define KW    (NKV*HDIM)           // 512

// ---------------------------------------------------------------------------
// Scratch (device globals; no allocations allowed)
// ---------------------------------------------------------------------------
__device__ float g_q[MROWS * QW];                 // 32 MB fp32
__device__ float g_k[MROWS * KW];                 // 8 MB
__device__ float g_v[MROWS * KW];                 // 8 MB
__device__ float g_att[MROWS * QW];               // 32 MB
__device__ __nv_bfloat16 g_x2 [4096 * 4096];      // 32 MB (x split, later att split)
__device__ __nv_bfloat16 g_wq2[2048 * 4096];      // 16 MB
__device__ __nv_bfloat16 g_wk2[ 512 * 4096];      // 4 MB
__device__ __nv_bfloat16 g_wv2[ 512 * 4096];      // 4 MB
__device__ __nv_bfloat16 g_wo2[2048 * 4096];      // 16 MB

// ---------------------------------------------------------------------------
// Baseline-PTX tensor-core helpers (mma.sync / ldmatrix / cp.async)
// ---------------------------------------------------------------------------
__device__ __forceinline__ uint32_t smem_u32_of(const void* p) {
    uint32_t a;
    asm("{ .reg .u64 t; cvta.to.shared.u64 t, %1; cvt.u32.u64 %0, t; }" : "=r"(a) : "l"(p));
    return a;
}
__device__ __forceinline__ void cp_async16(uint32_t saddr, const void* gaddr) {
    asm volatile("cp.async.cg.shared.global [%0], [%1], 16;" :: "r"(saddr), "l"(gaddr));
}
__device__ __forceinline__ void cp_commit() {
    asm volatile("cp.async.commit_group;" ::: "memory");
}
__device__ __forceinline__ void cp_wait1() {
    asm volatile("cp.async.wait_group 1;" ::: "memory");
}
__device__ __forceinline__ void cp_wait0() {
    asm volatile("cp.async.wait_group 0;" ::: "memory");
}
__device__ __forceinline__ void ldmatrix_x4(uint32_t* r, uint32_t addr) {
    asm volatile("ldmatrix.sync.aligned.m8n8.x4.shared.b16 {%0,%1,%2,%3}, [%4];"
                 : "=r"(r[0]), "=r"(r[1]), "=r"(r[2]), "=r"(r[3]) : "r"(addr));
}
__device__ __forceinline__ void mma_bf16(float* c, const uint32_t* a, uint32_t b0, uint32_t b1) {
    asm volatile(
        "mma.sync.aligned.m16n8k16.row.col.f32.bf16.bf16.f32 "
        "{%0,%1,%2,%3}, {%4,%5,%6,%7}, {%8,%9}, {%0,%1,%2,%3};"
        : "+f"(c[0]), "+f"(c[1]), "+f"(c[2]), "+f"(c[3])
        : "r"(a[0]), "r"(a[1]), "r"(a[2]), "r"(a[3]), "r"(b0), "r"(b1));
}

// ---------------------------------------------------------------------------
// HMMA split-bf16 GEMM: C[M,N] = A[M,K]*B[K,N] (+bias) with
//   A2[M, 2K] = [A_hi | A_lo],  B2[N, 2K] = [Bt_hi | Bt_lo] (K-major)
// computed as Ah*Bh + Al*Bh + Ah*Bl (3 K-segments).  K fixed 2048.
// 128x128 CTA tile, BK=64, 8 warps (warp tile 64x32), cp.async double buffer.
// SW128-swizzled smem tiles (128-byte rows).
// ---------------------------------------------------------------------------
#define HG_SMEM 65536

__global__ __launch_bounds__(256, 1)
void hgemm_kernel(const __nv_bfloat16* __restrict__ A2, const __nv_bfloat16* __restrict__ B2,
                  float* __restrict__ C, int N, const float* __restrict__ bias)
{
    extern __shared__ __align__(1024) char smem[];
    const uint32_t su = smem_u32_of(smem);
    const int tid  = threadIdx.x;
    const int wid  = tid >> 5;
    const int lane = tid & 31;
    const int m0 = blockIdx.y * 128;
    const int n0 = blockIdx.x * 128;
    const int ld = 4096;                 // 2*K

    // cp.async slots: 4 A chunks + 4 B chunks of 16B per thread per iter
    uint32_t smoff[4];
    const __nv_bfloat16 *gA[4], *gB[4];
#pragma unroll
    for (int i = 0; i < 4; i++) {
        int id = tid + i * 256;
        int r = id >> 3, c = id & 7;                       // row 0..127, 16B chunk 0..7
        smoff[i] = (uint32_t)(r * 128 + ((c ^ (r & 7)) << 4));
        gA[i] = A2 + (size_t)(m0 + r) * ld + c * 8;
        gB[i] = B2 + (size_t)(n0 + r) * ld + c * 8;
    }

    const int mwarp = (wid >> 2) * 64;
    const int nwarp = (wid & 3) * 32;

    // ldmatrix lane addressing (within-tile, before stage offset)
    const int asel = lane >> 3;                            // 0..3
    const int arow = (lane & 7) + ((asel & 1) << 3);       // A: row within m16
    const int akc  = asel >> 1;                            // A: k-chunk add (0/1)
    const int brow = (lane & 7) + ((asel >> 1) << 3);      // B: row within n16
    const int bkc  = asel & 1;                             // B: k-chunk add

    float acc[4][4][4];
#pragma unroll
    for (int mf = 0; mf < 4; mf++)
#pragma unroll
        for (int nf = 0; nf < 4; nf++)
#pragma unroll
            for (int e = 0; e < 4; e++) acc[mf][nf][e] = 0.f;

    const int NIT = 96;                                    // 3 segments x 32 chunks

    // issue loads for iteration `it` into stage it&1
    auto issue = [&](int it) {
        int seg = it >> 5;
        int t   = it & 31;
        int aoff = t * 64 + (seg == 1 ? 2048 : 0);
        int boff = t * 64 + (seg == 2 ? 2048 : 0);
        uint32_t ab = su + (uint32_t)(it & 1) * 32768u;
        uint32_t bb = ab + 16384u;
#pragma unroll
        for (int i = 0; i < 4; i++) {
            cp_async16(ab + smoff[i], gA[i] + aoff);
            cp_async16(bb + smoff[i], gB[i] + boff);
        }
        cp_commit();
    };

    issue(0);
    for (int it = 0; it < NIT; ++it) {
        if (it + 1 < NIT) { issue(it + 1); cp_wait1(); }
        else              { cp_wait0(); }
        __syncthreads();

        uint32_t abase = su + (uint32_t)(it & 1) * 32768u;
        uint32_t bbase = abase + 16384u;

#pragma unroll
        for (int ks = 0; ks < 4; ++ks) {
            uint32_t ar[4][4];
#pragma unroll
            for (int mf = 0; mf < 4; mf++) {
                int R = mwarp + mf * 16 + arow;
                int ch = ks * 2 + akc;
                ldmatrix_x4(ar[mf], abase + R * 128 + (uint32_t)((ch ^ (R & 7)) << 4));
            }
            uint32_t br[2][4];
#pragma unroll
            for (int bh = 0; bh < 2; bh++) {
                int R = nwarp + bh * 16 + brow;
                int ch = ks * 2 + bkc;
                ldmatrix_x4(br[bh], bbase + R * 128 + (uint32_t)((ch ^ (R & 7)) << 4));
            }
#pragma unroll
            for (int mf = 0; mf < 4; mf++) {
#pragma unroll
                for (int bh = 0; bh < 2; bh++) {
                    mma_bf16(acc[mf][bh * 2 + 0], ar[mf], br[bh][0], br[bh][1]);
                    mma_bf16(acc[mf][bh * 2 + 1], ar[mf], br[bh][2], br[bh][3]);
                }
            }
        }
        __syncthreads();
    }

    // epilogue
    const int mrow = lane >> 2;
    const int ncol = (lane & 3) * 2;
#pragma unroll
    for (int mf = 0; mf < 4; mf++) {
#pragma unroll
        for (int nf = 0; nf < 4; nf++) {
            int gm = m0 + mwarp + mf * 16 + mrow;
            int gn = n0 + nwarp + nf * 8 + ncol;
            float b0 = 0.f, b1 = 0.f;
            if (bias != nullptr) { b0 = bias[gn]; b1 = bias[gn + 1]; }
            float2 lo = make_float2(acc[mf][nf][0] + b0, acc[mf][nf][1] + b1);
            float2 hi = make_float2(acc[mf][nf][2] + b0, acc[mf][nf][3] + b1);
            *reinterpret_cast<float2*>(C + (size_t)gm * N + gn)       = lo;
            *reinterpret_cast<float2*>(C + (size_t)(gm + 8) * N + gn) = hi;
        }
    }
}

// ---------------------------------------------------------------------------
// fp32 -> (hi, lo) bf16 split. src [M, 2048] -> dst [M, 4096] ([hi|lo]).
// ---------------------------------------------------------------------------
__global__ void split2048_kernel(const float* __restrict__ src, __nv_bfloat16* __restrict__ dst)
{
    int i = blockIdx.x * 256 + threadIdx.x;      // float4 index
    float4 v = reinterpret_cast<const float4*>(src)[i];
    int e = i * 4;
    int m = e >> 11;
    int k = e & 2047;
    __nv_bfloat16* d = dst + (size_t)m * 4096 + k;
    __nv_bfloat16 h0 = __float2bfloat16(v.x), h1 = __float2bfloat16(v.y);
    __nv_bfloat16 h2 = __float2bfloat16(v.z), h3 = __float2bfloat16(v.w);
    d[0] = h0; d[1] = h1; d[2] = h2; d[3] = h3;
    d[2048] = __float2bfloat16(v.x - __bfloat162float(h0));
    d[2049] = __float2bfloat16(v.y - __bfloat162float(h1));
    d[2050] = __float2bfloat16(v.z - __bfloat162float(h2));
    d[2051] = __float2bfloat16(v.w - __bfloat162float(h3));
}

// ---------------------------------------------------------------------------
// W [2048, N] fp32 -> transposed split dst [N, 4096] ([hi|lo], K-major).
// ---------------------------------------------------------------------------
__global__ void tsplit2048_kernel(const float* __restrict__ W, __nv_bfloat16* __restrict__ dst, int N)
{
    __shared__ float tl[32][33];
    int tx = threadIdx.x, ty = threadIdx.y;   // 32 x 8
    int n0 = blockIdx.x * 32, k0 = blockIdx.y * 32;
#pragma unroll
    for (int j = 0; j < 4; j++)
        tl[ty + j * 8][tx] = W[(size_t)(k0 + ty + j * 8) * N + n0 + tx];
    __syncthreads();
#pragma unroll
    for (int j = 0; j < 4; j++) {
        int n = n0 + ty + j * 8;
        int k = k0 + tx;
        float v = tl[tx][ty + j * 8];
        __nv_bfloat16 h = __float2bfloat16(v);
        dst[(size_t)n * 4096 + k] = h;
        dst[(size_t)n * 4096 + 2048 + k] = __float2bfloat16(v - __bfloat162float(h));
    }
}

// ---------------------------------------------------------------------------
// RMSNorm + RoPE, in-place on q and k.
// ---------------------------------------------------------------------------
__global__ void norm_rope_kernel(float* __restrict__ q, float* __restrict__ k,
                                 const float* __restrict__ cosp,
                                 const float* __restrict__ sinp)
{
    const long bid = blockIdx.x;
    const int  d   = threadIdx.x;   // 0..127
    float* row;
    int t;
    if (bid < (long)MROWS * NHEAD) {
        int bt = (int)(bid / NHEAD);
        int h  = (int)(bid % NHEAD);
        t = bt % SEQ;
        row = q + (size_t)bt * QW + h * HDIM;
    } else {
        long r = bid - (long)MROWS * NHEAD;
        int bt = (int)(r / NKV);
        int h  = (int)(r % NKV);
        t = bt % SEQ;
        row = k + (size_t)bt * KW + h * HDIM;
    }

    float val = row[d];
    float ss  = val * val;
#pragma unroll
    for (int off = 16; off; off >>= 1)
        ss += __shfl_xor_sync(0xffffffffu, ss, off);

    __shared__ float red[4];
    if ((d & 31) == 0) red[d >> 5] = ss;
    __syncthreads();
    float total = red[0] + red[1] + red[2] + red[3];
    float rms = rsqrtf(total * (1.0f / 128.0f) + 1.1920929e-7f);
    val *= rms;

    __shared__ float sh[128];
    sh[d] = val;
    __syncthreads();

    float out;
    if (d < HALF) {
        float c = cosp[t * HALF + d], s = sinp[t * HALF + d];
        out = val * c - sh[d + HALF] * s;
    } else {
        int f = d - HALF;
        float c = cosp[t * HALF + f], s = sinp[t * HALF + f];
        out = sh[f] * s + val * c;
    }
    row[d] = out;
}

// ---------------------------------------------------------------------------
// Flash attention, causal, GQA. 64x64 tiles, D=128, fp32 online softmax.
// ---------------------------------------------------------------------------
#define FBM 64
#define FBN 64
#define QPITCH 132
#define SPITCH 68
#define ATTN_SMEM ((3 * FBM * QPITCH + FBM * SPITCH + 3 * FBM) * 4)

__global__ __launch_bounds__(256)
void flash_attn_kernel(const float* __restrict__ q, const float* __restrict__ k,
                       const float* __restrict__ v, float* __restrict__ att)
{
    extern __shared__ float sm[];
    float* Qs   = sm;
    float* Ks   = Qs + FBM * QPITCH;
    float* Vs   = Ks + FBM * QPITCH;
    float* Ss   = Vs + FBM * QPITCH;
    float* mrow = Ss + FBM * SPITCH;
    float* lrow = mrow + FBM;
    float* arow = lrow + FBM;

    const int qt  = blockIdx.x;
    const int bh  = blockIdx.y;
    const int b   = bh >> 4;
    const int h   = bh & 15;
    const int hkv = h >> 2;
    const int tid = threadIdx.x;
    const int ty  = tid >> 4;
    const int tx  = tid & 15;
    const int q0  = qt * FBM;
    const float scale = 0.08838834764831845f;

    const float* qbase = q + (size_t)b * SEQ * QW + h   * HDIM;
    const float* kbase = k + (size_t)b * SEQ * KW + hkv * HDIM;
    const float* vbase = v + (size_t)b * SEQ * KW + hkv * HDIM;

    for (int i = tid; i < FBM * 32; i += 256) {
        int r = i >> 5, c4 = i & 31;
        *reinterpret_cast<float4*>(&Qs[r * QPITCH + c4 * 4]) =
            *reinterpret_cast<const float4*>(qbase + (size_t)(q0 + r) * QW + c4 * 4);
    }
    if (tid < FBM) { mrow[tid] = -1e30f; lrow[tid] = 0.f; }

    float o[4][8];
#pragma unroll
    for (int i = 0; i < 4; i++)
#pragma unroll
        for (int j = 0; j < 8; j++) o[i][j] = 0.f;

    const int ntiles = qt + 1;
    for (int kt = 0; kt < ntiles; ++kt) {
        const int k0 = kt * FBN;
        __syncthreads();
        for (int i = tid; i < FBN * 32; i += 256) {
            int r = i >> 5, c4 = i & 31;
            *reinterpret_cast<float4*>(&Ks[r * QPITCH + c4 * 4]) =
                *reinterpret_cast<const float4*>(kbase + (size_t)(k0 + r) * KW + c4 * 4);
            *reinterpret_cast<float4*>(&Vs[r * QPITCH + c4 * 4]) =
                *reinterpret_cast<const float4*>(vbase + (size_t)(k0 + r) * KW + c4 * 4);
        }
        __syncthreads();

        float s[4][4];
#pragma unroll
        for (int i = 0; i < 4; i++)
#pragma unroll
            for (int j = 0; j < 4; j++) s[i][j] = 0.f;

        for (int dd = 0; dd < HDIM; dd += 4) {
            float4 qv[4], kv[4];
#pragma unroll
            for (int i = 0; i < 4; i++)
                qv[i] = *reinterpret_cast<const float4*>(&Qs[(ty * 4 + i) * QPITCH + dd]);
#pragma unroll
            for (int j = 0; j < 4; j++)
                kv[j] = *reinterpret_cast<const float4*>(&Ks[(tx + 16 * j) * QPITCH + dd]);
#pragma unroll
            for (int i = 0; i < 4; i++)
#pragma unroll
                for (int j = 0; j < 4; j++) {
                    s[i][j] += qv[i].x * kv[j].x;
                    s[i][j] += qv[i].y * kv[j].y;
                    s[i][j] += qv[i].z * kv[j].z;
                    s[i][j] += qv[i].w * kv[j].w;
                }
        }

        const bool diag = (kt == qt);
#pragma unroll
        for (int i = 0; i < 4; i++) {
            int r = ty * 4 + i;
#pragma unroll
            for (int j = 0; j < 4; j++) {
                int c = tx + 16 * j;
                float val = s[i][j] * scale;
                if (diag && (k0 + c > q0 + r)) val = -1e30f;
                s[i][j] = val;
                Ss[r * SPITCH + c] = val;
            }
        }
        __syncthreads();

        if (tid < FBM) {
            float mx = -1e30f;
            const float* srow = &Ss[tid * SPITCH];
            for (int c = 0; c < FBN; c++) mx = fmaxf(mx, srow[c]);
            float m_new = fmaxf(mrow[tid], mx);
            arow[tid] = __expf(mrow[tid] - m_new);
            mrow[tid] = m_new;
        }
        __syncthreads();

#pragma unroll
        for (int i = 0; i < 4; i++) {
            int r = ty * 4 + i;
            float mn = mrow[r];
#pragma unroll
            for (int j = 0; j < 4; j++)
                Ss[r * SPITCH + tx + 16 * j] = __expf(s[i][j] - mn);
        }
#pragma unroll
        for (int i = 0; i < 4; i++) {
            float a = arow[ty * 4 + i];
#pragma unroll
            for (int j = 0; j < 8; j++) o[i][j] *= a;
        }
        __syncthreads();

        if (tid < FBM) {
            float sum = 0.f;
            const float* srow = &Ss[tid * SPITCH];
            for (int c = 0; c < FBN; c++) sum += srow[c];
            lrow[tid] = arow[tid] * lrow[tid] + sum;
        }

        for (int c = 0; c < FBN; c++) {
            float pv[4];
#pragma unroll
            for (int i = 0; i < 4; i++) pv[i] = Ss[(ty * 4 + i) * SPITCH + c];
            float4 v0 = *reinterpret_cast<const float4*>(&Vs[c * QPITCH + tx * 8]);
            float4 v1 = *reinterpret_cast<const float4*>(&Vs[c * QPITCH + tx * 8 + 4]);
#pragma unroll
            for (int i = 0; i < 4; i++) {
                o[i][0] += pv[i] * v0.x; o[i][1] += pv[i] * v0.y;
                o[i][2] += pv[i] * v0.z; o[i][3] += pv[i] * v0.w;
                o[i][4] += pv[i] * v1.x; o[i][5] += pv[i] * v1.y;
                o[i][6] += pv[i] * v1.z; o[i][7] += pv[i] * v1.w;
            }
        }
    }
    __syncthreads();

#pragma unroll
    for (int i = 0; i < 4; i++) {
        int r = ty * 4 + i;
        float inv = 1.0f / lrow[r];
        float* op = att + (size_t)(b * SEQ + q0 + r) * QW + h * HDIM + tx * 8;
        float4 r0, r1;
        r0.x = o[i][0] * inv; r0.y = o[i][1] * inv;
        r0.z = o[i][2] * inv; r0.w = o[i][3] * inv;
        r1.x = o[i][4] * inv; r1.y = o[i][5] * inv;
        r1.z = o[i][6] * inv; r1.w = o[i][7] * inv;
        *reinterpret_cast<float4*>(op)     = r0;
        *reinterpret_cast<float4*>(op + 4) = r1;
    }
}

// ---------------------------------------------------------------------------
// Launch
// ---------------------------------------------------------------------------
extern "C" void kernel_launch(void* const* d_in, const int* in_sizes, int n_in,
                              void* d_out, int out_size)
{
    const float* x    = (const float*)d_in[0];
    const float* cosp = (const float*)d_in[1];
    const float* sinp = (const float*)d_in[2];
    const float* Wq   = (const float*)d_in[3];
    const float* Wk   = (const float*)d_in[4];
    const float* Wv   = (const float*)d_in[5];
    const float* Wo   = (const float*)d_in[6];
    const float* bo   = (const float*)d_in[7];
    float* out = (float*)d_out;

    float *qs, *ks, *vs, *att;
    __nv_bfloat16 *x2, *wq2, *wk2, *wv2, *wo2;
    cudaGetSymbolAddress((void**)&qs,  g_q);
    cudaGetSymbolAddress((void**)&ks,  g_k);
    cudaGetSymbolAddress((void**)&vs,  g_v);
    cudaGetSymbolAddress((void**)&att, g_att);
    cudaGetSymbolAddress((void**)&x2,  g_x2);
    cudaGetSymbolAddress((void**)&wq2, g_wq2);
    cudaGetSymbolAddress((void**)&wk2, g_wk2);
    cudaGetSymbolAddress((void**)&wv2, g_wv2);
    cudaGetSymbolAddress((void**)&wo2, g_wo2);

    cudaFuncSetAttribute(hgemm_kernel, cudaFuncAttributeMaxDynamicSharedMemorySize, HG_SMEM);
    cudaFuncSetAttribute(flash_attn_kernel, cudaFuncAttributeMaxDynamicSharedMemorySize, ATTN_SMEM);

    // split conversions
    split2048_kernel<<<MROWS * CDIM / 4 / 256, 256>>>(x, x2);
    tsplit2048_kernel<<<dim3(QW / 32, CDIM / 32), dim3(32, 8)>>>(Wq, wq2, QW);
    tsplit2048_kernel<<<dim3(KW / 32, CDIM / 32), dim3(32, 8)>>>(Wk, wk2, KW);
    tsplit2048_kernel<<<dim3(KW / 32, CDIM / 32), dim3(32, 8)>>>(Wv, wv2, KW);
    tsplit2048_kernel<<<dim3(QW / 32, CDIM / 32), dim3(32, 8)>>>(Wo, wo2, QW);

    // QKV projections (HMMA tensor cores, bf16 split)
    hgemm_kernel<<<dim3(QW / 128, MROWS / 128), 256, HG_SMEM>>>(x2, wq2, qs, QW, nullptr);
    hgemm_kernel<<<dim3(KW / 128, MROWS / 128), 256, HG_SMEM>>>(x2, wk2, ks, KW, nullptr);
    hgemm_kernel<<<dim3(KW / 128, MROWS / 128), 256, HG_SMEM>>>(x2, wv2, vs, KW, nullptr);

    // RMSNorm + RoPE (in place)
    norm_rope_kernel<<<MROWS * (NHEAD + NKV), 128>>>(qs, ks, cosp, sinp);

    // Flash attention (fp32)
    dim3 ga(SEQ / FBM, BATCH * NHEAD);
    flash_attn_kernel<<<ga, 256, ATTN_SMEM>>>(qs, ks, vs, att);

    // attention output split, then output projection + bias
    split2048_kernel<<<MROWS * CDIM / 4 / 256, 256>>>(att, x2);
    hgemm_kernel<<<dim3(QW / 128, MROWS / 128), 256, HG_SMEM>>>(x2, wo2, out, QW, bo);
}

// round 6
// speedup vs baseline: 3.1473x; 1.8089x over previous
#include <cuda_runtime.h>
#include <cuda_bf16.h>
#include <math.h>
#include <stdint.h>

// Problem constants
#define BATCH 2
#define SEQ   2048
#define CDIM  2048
#define NHEAD 16
#define NKV   4
#define HDIM  128
#define HALF  64
#define MROWS (BATCH*SEQ)          // 4096
#define QW    (NHEAD*HDIM)         // 2048
#define KW    (NKV*HDIM)           // 512

// ---------------------------------------------------------------------------
// Scratch (device globals; no allocations allowed)
// ---------------------------------------------------------------------------
__device__ float g_q[MROWS * QW];                 // 32 MB fp32 (pre-norm q)
__device__ float g_k[MROWS * KW];                 // 8 MB
__device__ float g_v[MROWS * KW];                 // 8 MB
__device__ __nv_bfloat16 g_x2 [4096 * 4096];      // 32 MB (x split; later attn-out split)
__device__ __nv_bfloat16 g_wq2[2048 * 4096];      // 16 MB
__device__ __nv_bfloat16 g_wk2[ 512 * 4096];      // 4 MB
__device__ __nv_bfloat16 g_wv2[ 512 * 4096];      // 4 MB
__device__ __nv_bfloat16 g_wo2[2048 * 4096];      // 16 MB
__device__ __nv_bfloat16 g_qh[MROWS * QW];        // 16 MB
__device__ __nv_bfloat16 g_ql[MROWS * QW];        // 16 MB
__device__ __nv_bfloat16 g_kh[MROWS * KW];        // 4 MB
__device__ __nv_bfloat16 g_kl[MROWS * KW];        // 4 MB
__device__ __nv_bfloat16 g_vh[MROWS * KW];        // 4 MB
__device__ __nv_bfloat16 g_vl[MROWS * KW];        // 4 MB

// ---------------------------------------------------------------------------
// Baseline-PTX tensor-core helpers
// ---------------------------------------------------------------------------
__device__ __forceinline__ uint32_t smem_u32_of(const void* p) {
    uint32_t a;
    asm("{ .reg .u64 t; cvta.to.shared.u64 t, %1; cvt.u32.u64 %0, t; }" : "=r"(a) : "l"(p));
    return a;
}
__device__ __forceinline__ void cp_async16(uint32_t saddr, const void* gaddr) {
    asm volatile("cp.async.cg.shared.global [%0], [%1], 16;" :: "r"(saddr), "l"(gaddr));
}
__device__ __forceinline__ void cp_commit() {
    asm volatile("cp.async.commit_group;" ::: "memory");
}
__device__ __forceinline__ void cp_wait1() {
    asm volatile("cp.async.wait_group 1;" ::: "memory");
}
__device__ __forceinline__ void cp_wait0() {
    asm volatile("cp.async.wait_group 0;" ::: "memory");
}
__device__ __forceinline__ void ldmatrix_x4(uint32_t* r, uint32_t addr) {
    asm volatile("ldmatrix.sync.aligned.m8n8.x4.shared.b16 {%0,%1,%2,%3}, [%4];"
                 : "=r"(r[0]), "=r"(r[1]), "=r"(r[2]), "=r"(r[3]) : "r"(addr));
}
__device__ __forceinline__ void ldmatrix_x4_trans(uint32_t* r, uint32_t addr) {
    asm volatile("ldmatrix.sync.aligned.m8n8.x4.trans.shared.b16 {%0,%1,%2,%3}, [%4];"
                 : "=r"(r[0]), "=r"(r[1]), "=r"(r[2]), "=r"(r[3]) : "r"(addr));
}
__device__ __forceinline__ void mma_bf16(float* c, const uint32_t* a, uint32_t b0, uint32_t b1) {
    asm volatile(
        "mma.sync.aligned.m16n8k16.row.col.f32.bf16.bf16.f32 "
        "{%0,%1,%2,%3}, {%4,%5,%6,%7}, {%8,%9}, {%0,%1,%2,%3};"
        : "+f"(c[0]), "+f"(c[1]), "+f"(c[2]), "+f"(c[3])
        : "r"(a[0]), "r"(a[1]), "r"(a[2]), "r"(a[3]), "r"(b0), "r"(b1));
}

// swizzled smem offsets (16B chunks, XOR row&7)
#define SW256(r, c) ((uint32_t)((r) * 256 + (((c) ^ ((r) & 7)) << 4)))
#define SW128(r, c) ((uint32_t)((r) * 128 + (((c) ^ ((r) & 7)) << 4)))

// ---------------------------------------------------------------------------
// HMMA split-bf16 GEMM: C = A*B (+bias)
//   A2[M,2K]=[hi|lo], B2[N,2K]=[hi|lo] K-major. 3 K-segments. K=2048.
// ---------------------------------------------------------------------------
#define HG_SMEM 65536

__global__ __launch_bounds__(256, 1)
void hgemm_kernel(const __nv_bfloat16* __restrict__ A2, const __nv_bfloat16* __restrict__ B2,
                  float* __restrict__ C, int N, const float* __restrict__ bias)
{
    extern __shared__ __align__(1024) char smem[];
    const uint32_t su = smem_u32_of(smem);
    const int tid  = threadIdx.x;
    const int wid  = tid >> 5;
    const int lane = tid & 31;
    const int m0 = blockIdx.y * 128;
    const int n0 = blockIdx.x * 128;
    const int ld = 4096;

    uint32_t smoff[4];
    const __nv_bfloat16 *gA[4], *gB[4];
#pragma unroll
    for (int i = 0; i < 4; i++) {
        int id = tid + i * 256;
        int r = id >> 3, c = id & 7;
        smoff[i] = (uint32_t)(r * 128 + ((c ^ (r & 7)) << 4));
        gA[i] = A2 + (size_t)(m0 + r) * ld + c * 8;
        gB[i] = B2 + (size_t)(n0 + r) * ld + c * 8;
    }

    const int mwarp = (wid >> 2) * 64;
    const int nwarp = (wid & 3) * 32;

    const int asel = lane >> 3;
    const int arow = (lane & 7) + ((asel & 1) << 3);
    const int akc  = asel >> 1;
    const int brow = (lane & 7) + ((asel >> 1) << 3);
    const int bkc  = asel & 1;

    float acc[4][4][4];
#pragma unroll
    for (int mf = 0; mf < 4; mf++)
#pragma unroll
        for (int nf = 0; nf < 4; nf++)
#pragma unroll
            for (int e = 0; e < 4; e++) acc[mf][nf][e] = 0.f;

    const int NIT = 96;

    auto issue = [&](int it) {
        int seg = it >> 5;
        int t   = it & 31;
        int aoff = t * 64 + (seg == 1 ? 2048 : 0);
        int boff = t * 64 + (seg == 2 ? 2048 : 0);
        uint32_t ab = su + (uint32_t)(it & 1) * 32768u;
        uint32_t bb = ab + 16384u;
#pragma unroll
        for (int i = 0; i < 4; i++) {
            cp_async16(ab + smoff[i], gA[i] + aoff);
            cp_async16(bb + smoff[i], gB[i] + boff);
        }
        cp_commit();
    };

    issue(0);
    for (int it = 0; it < NIT; ++it) {
        if (it + 1 < NIT) { issue(it + 1); cp_wait1(); }
        else              { cp_wait0(); }
        __syncthreads();

        uint32_t abase = su + (uint32_t)(it & 1) * 32768u;
        uint32_t bbase = abase + 16384u;

#pragma unroll
        for (int ks = 0; ks < 4; ++ks) {
            uint32_t ar[4][4];
#pragma unroll
            for (int mf = 0; mf < 4; mf++) {
                int R = mwarp + mf * 16 + arow;
                int ch = ks * 2 + akc;
                ldmatrix_x4(ar[mf], abase + R * 128 + (uint32_t)((ch ^ (R & 7)) << 4));
            }
            uint32_t br[2][4];
#pragma unroll
            for (int bh = 0; bh < 2; bh++) {
                int R = nwarp + bh * 16 + brow;
                int ch = ks * 2 + bkc;
                ldmatrix_x4(br[bh], bbase + R * 128 + (uint32_t)((ch ^ (R & 7)) << 4));
            }
#pragma unroll
            for (int mf = 0; mf < 4; mf++) {
#pragma unroll
                for (int bh = 0; bh < 2; bh++) {
                    mma_bf16(acc[mf][bh * 2 + 0], ar[mf], br[bh][0], br[bh][1]);
                    mma_bf16(acc[mf][bh * 2 + 1], ar[mf], br[bh][2], br[bh][3]);
                }
            }
        }
        __syncthreads();
    }

    const int mrow = lane >> 2;
    const int ncol = (lane & 3) * 2;
#pragma unroll
    for (int mf = 0; mf < 4; mf++) {
#pragma unroll
        for (int nf = 0; nf < 4; nf++) {
            int gm = m0 + mwarp + mf * 16 + mrow;
            int gn = n0 + nwarp + nf * 8 + ncol;
            float b0 = 0.f, b1 = 0.f;
            if (bias != nullptr) { b0 = bias[gn]; b1 = bias[gn + 1]; }
            float2 lo = make_float2(acc[mf][nf][0] + b0, acc[mf][nf][1] + b1);
            float2 hi = make_float2(acc[mf][nf][2] + b0, acc[mf][nf][3] + b1);
            *reinterpret_cast<float2*>(C + (size_t)gm * N + gn)       = lo;
            *reinterpret_cast<float2*>(C + (size_t)(gm + 8) * N + gn) = hi;
        }
    }
}

// ---------------------------------------------------------------------------
// fp32 -> (hi, lo) bf16 split. src [M, 2048] -> dst [M, 4096] ([hi|lo]).
// ---------------------------------------------------------------------------
__global__ void split2048_kernel(const float* __restrict__ src, __nv_bfloat16* __restrict__ dst)
{
    int i = blockIdx.x * 256 + threadIdx.x;
    float4 v = reinterpret_cast<const float4*>(src)[i];
    int e = i * 4;
    int m = e >> 11;
    int k = e & 2047;
    __nv_bfloat16* d = dst + (size_t)m * 4096 + k;
    __nv_bfloat16 h0 = __float2bfloat16(v.x), h1 = __float2bfloat16(v.y);
    __nv_bfloat16 h2 = __float2bfloat16(v.z), h3 = __float2bfloat16(v.w);
    d[0] = h0; d[1] = h1; d[2] = h2; d[3] = h3;
    d[2048] = __float2bfloat16(v.x - __bfloat162float(h0));
    d[2049] = __float2bfloat16(v.y - __bfloat162float(h1));
    d[2050] = __float2bfloat16(v.z - __bfloat162float(h2));
    d[2051] = __float2bfloat16(v.w - __bfloat162float(h3));
}

// ---------------------------------------------------------------------------
// W [2048, N] fp32 -> transposed split dst [N, 4096] ([hi|lo], K-major).
// ---------------------------------------------------------------------------
__global__ void tsplit2048_kernel(const float* __restrict__ W, __nv_bfloat16* __restrict__ dst, int N)
{
    __shared__ float tl[32][33];
    int tx = threadIdx.x, ty = threadIdx.y;
    int n0 = blockIdx.x * 32, k0 = blockIdx.y * 32;
#pragma unroll
    for (int j = 0; j < 4; j++)
        tl[ty + j * 8][tx] = W[(size_t)(k0 + ty + j * 8) * N + n0 + tx];
    __syncthreads();
#pragma unroll
    for (int j = 0; j < 4; j++) {
        int n = n0 + ty + j * 8;
        int k = k0 + tx;
        float v = tl[tx][ty + j * 8];
        __nv_bfloat16 h = __float2bfloat16(v);
        dst[(size_t)n * 4096 + k] = h;
        dst[(size_t)n * 4096 + 2048 + k] = __float2bfloat16(v - __bfloat162float(h));
    }
}

// ---------------------------------------------------------------------------
// RMSNorm + RoPE: read fp32 q/k, write bf16 hi/lo splits.
// ---------------------------------------------------------------------------
__global__ void norm_rope_split_kernel(const float* __restrict__ q, const float* __restrict__ k,
                                       const float* __restrict__ cosp, const float* __restrict__ sinp,
                                       __nv_bfloat16* __restrict__ qh, __nv_bfloat16* __restrict__ ql,
                                       __nv_bfloat16* __restrict__ kh, __nv_bfloat16* __restrict__ kl)
{
    const long bid = blockIdx.x;
    const int  d   = threadIdx.x;   // 0..127
    const float* row;
    __nv_bfloat16 *oh, *ol;
    int t;
    if (bid < (long)MROWS * NHEAD) {
        int bt = (int)(bid / NHEAD);
        int h  = (int)(bid % NHEAD);
        t = bt % SEQ;
        size_t off = (size_t)bt * QW + h * HDIM;
        row = q + off; oh = qh + off; ol = ql + off;
    } else {
        long r = bid - (long)MROWS * NHEAD;
        int bt = (int)(r / NKV);
        int h  = (int)(r % NKV);
        t = bt % SEQ;
        size_t off = (size_t)bt * KW + h * HDIM;
        row = k + off; oh = kh + off; ol = kl + off;
    }

    float val = row[d];
    float ss  = val * val;
#pragma unroll
    for (int off = 16; off; off >>= 1)
        ss += __shfl_xor_sync(0xffffffffu, ss, off);

    __shared__ float red[4];
    if ((d & 31) == 0) red[d >> 5] = ss;
    __syncthreads();
    float total = red[0] + red[1] + red[2] + red[3];
    float rms = rsqrtf(total * (1.0f / 128.0f) + 1.1920929e-7f);
    val *= rms;

    __shared__ float sh[128];
    sh[d] = val;
    __syncthreads();

    float out;
    if (d < HALF) {
        float c = cosp[t * HALF + d], s = sinp[t * HALF + d];
        out = val * c - sh[d + HALF] * s;
    } else {
        int f = d - HALF;
        float c = cosp[t * HALF + f], s = sinp[t * HALF + f];
        out = sh[f] * s + val * c;
    }
    __nv_bfloat16 h = __float2bfloat16(out);
    oh[d] = h;
    ol[d] = __float2bfloat16(out - __bfloat162float(h));
}

// ---------------------------------------------------------------------------
// v fp32 -> bf16 hi + lo
// ---------------------------------------------------------------------------
__global__ void vsplit_kernel(const float* __restrict__ v, __nv_bfloat16* __restrict__ vh,
                              __nv_bfloat16* __restrict__ vl)
{
    int i = blockIdx.x * 256 + threadIdx.x;
    float4 x = reinterpret_cast<const float4*>(v)[i];
    __nv_bfloat16 h0 = __float2bfloat16(x.x), h1 = __float2bfloat16(x.y);
    __nv_bfloat16 h2 = __float2bfloat16(x.z), h3 = __float2bfloat16(x.w);
    __nv_bfloat162 a = {h0, h1}, b = {h2, h3};
    __nv_bfloat162 la = {__float2bfloat16(x.x - __bfloat162float(h0)),
                         __float2bfloat16(x.y - __bfloat162float(h1))};
    __nv_bfloat162 lb = {__float2bfloat16(x.z - __bfloat162float(h2)),
                         __float2bfloat16(x.w - __bfloat162float(h3))};
    reinterpret_cast<__nv_bfloat162*>(vh)[i * 2]     = a;
    reinterpret_cast<__nv_bfloat162*>(vh)[i * 2 + 1] = b;
    reinterpret_cast<__nv_bfloat162*>(vl)[i * 2]     = la;
    reinterpret_cast<__nv_bfloat162*>(vl)[i * 2 + 1] = lb;
}

// ---------------------------------------------------------------------------
// HMMA flash attention, causal, GQA.
//   BM=128 q rows per CTA, BN=64 keys per iteration, D=128.
//   8 warps, each owns m16 x full n64 (softmax reductions intra-warp).
//   S = qh*kh + ql*kh + qh*kl.   O += ph*vh + pl*vh + ph*vl.
//   Output written as bf16 hi/lo split directly into x2 (Wo GEMM input).
// Smem: Qhi 32K | Qlo 32K | K 2st hi/lo 64K | V 2st hi/lo 64K | Phi 16K | Plo 16K
// ---------------------------------------------------------------------------
#define FA_QHI 0
#define FA_QLO 32768
#define FA_K   65536
#define FA_V   131072
#define FA_PHI 196608
#define FA_PLO 212992
#define FA_SMEM 229376

__global__ __launch_bounds__(256, 1)
void flash_hmma_kernel(const __nv_bfloat16* __restrict__ qh, const __nv_bfloat16* __restrict__ ql,
                       const __nv_bfloat16* __restrict__ kh, const __nv_bfloat16* __restrict__ kl,
                       const __nv_bfloat16* __restrict__ vh, const __nv_bfloat16* __restrict__ vl,
                       __nv_bfloat16* __restrict__ x2)
{
    extern __shared__ __align__(1024) char smem[];
    const uint32_t su = smem_u32_of(smem);
    const int tid  = threadIdx.x;
    const int wid  = tid >> 5;
    const int lane = tid & 31;

    const int qt = (int)gridDim.x - 1 - (int)blockIdx.x;   // long CTAs first
    const int bh = blockIdx.y;
    const int b  = bh >> 4;
    const int h  = bh & 15;
    const int hkv = h >> 2;
    const int q0 = qt * 128;
    const float scale = 0.08838834764831845f;   // 1/sqrt(128)

    const __nv_bfloat16* qhb = qh + (size_t)b * SEQ * QW + h * HDIM;
    const __nv_bfloat16* qlb = ql + (size_t)b * SEQ * QW + h * HDIM;
    const __nv_bfloat16* khb = kh + (size_t)b * SEQ * KW + hkv * HDIM;
    const __nv_bfloat16* klb = kl + (size_t)b * SEQ * KW + hkv * HDIM;
    const __nv_bfloat16* vhb = vh + (size_t)b * SEQ * KW + hkv * HDIM;
    const __nv_bfloat16* vlb = vl + (size_t)b * SEQ * KW + hkv * HDIM;

    // load Q hi/lo (128 rows x 16 chunks each)
    for (int i = tid; i < 128 * 16; i += 256) {
        int r = i >> 4, c = i & 15;
        *reinterpret_cast<uint4*>(smem + FA_QHI + SW256(r, c)) =
            *reinterpret_cast<const uint4*>(qhb + (size_t)(q0 + r) * QW + c * 8);
        *reinterpret_cast<uint4*>(smem + FA_QLO + SW256(r, c)) =
            *reinterpret_cast<const uint4*>(qlb + (size_t)(q0 + r) * QW + c * 8);
    }

    // ldmatrix lane decomposition
    const int asel = lane >> 3;                       // 0..3
    const int arow = (lane & 7) + ((asel & 1) << 3);  // A-operand row within m16
    const int akc  = asel >> 1;                       // A k-chunk add
    const int brow = (lane & 7) + ((asel >> 1) << 3); // B-operand row within n16
    const int bkc  = asel & 1;
    const int qrow_s = wid * 16 + arow;               // smem row for Q/P ldmatrix

    float o[16][4];
#pragma unroll
    for (int g = 0; g < 16; g++)
#pragma unroll
        for (int e = 0; e < 4; e++) o[g][e] = 0.f;
    float m0 = -1e30f, m1 = -1e30f, l0 = 0.f, l1 = 0.f;

    const int ntiles = 2 * qt + 2;

    // K/V stage loaders (cp.async): kh, kl, vh, vl tiles (16KB each)
    auto issueKV = [&](int kt) {
        int k0 = kt * 64;
        uint32_t kbH = su + FA_K + (uint32_t)(kt & 1) * 32768u;
        uint32_t kbL = kbH + 16384u;
        uint32_t vbH = su + FA_V + (uint32_t)(kt & 1) * 32768u;
        uint32_t vbL = vbH + 16384u;
#pragma unroll
        for (int i = 0; i < 4; i++) {
            int id = tid + i * 256;
            int r = id >> 4, c = id & 15;
            size_t go = (size_t)(k0 + r) * KW + c * 8;
            uint32_t so = SW256(r, c);
            cp_async16(kbH + so, khb + go);
            cp_async16(kbL + so, klb + go);
            cp_async16(vbH + so, vhb + go);
            cp_async16(vbL + so, vlb + go);
        }
        cp_commit();
    };

    issueKV(0);

    const int r0g = q0 + wid * 16 + (lane >> 2);
    const int r1g = r0g + 8;
    const int pr0 = wid * 16 + (lane >> 2);
    const int pr1 = pr0 + 8;

    for (int kt = 0; kt < ntiles; ++kt) {
        if (kt + 1 < ntiles) { issueKV(kt + 1); cp_wait1(); }
        else                 { cp_wait0(); }
        __syncthreads();

        uint32_t kbH = su + FA_K + (uint32_t)(kt & 1) * 32768u;
        uint32_t kbL = kbH + 16384u;
        uint32_t vbH = su + FA_V + (uint32_t)(kt & 1) * 32768u;
        uint32_t vbL = vbH + 16384u;

        // ---- S = QK^T (split, 3 terms) ----
        float s[8][4];
#pragma unroll
        for (int t = 0; t < 8; t++)
#pragma unroll
            for (int e = 0; e < 4; e++) s[t][e] = 0.f;

#pragma unroll
        for (int d = 0; d < 8; ++d) {
            uint32_t ah[4], al[4];
            ldmatrix_x4(ah, su + FA_QHI + SW256(qrow_s, d * 2 + akc));
            ldmatrix_x4(al, su + FA_QLO + SW256(qrow_s, d * 2 + akc));
#pragma unroll
            for (int j = 0; j < 4; ++j) {
                int R = j * 16 + brow;
                uint32_t bhf[4], blf[4];
                ldmatrix_x4(bhf, kbH + SW256(R, d * 2 + bkc));
                ldmatrix_x4(blf, kbL + SW256(R, d * 2 + bkc));
                mma_bf16(s[2 * j],     ah, bhf[0], bhf[1]);
                mma_bf16(s[2 * j + 1], ah, bhf[2], bhf[3]);
                mma_bf16(s[2 * j],     al, bhf[0], bhf[1]);
                mma_bf16(s[2 * j + 1], al, bhf[2], bhf[3]);
                mma_bf16(s[2 * j],     ah, blf[0], blf[1]);
                mma_bf16(s[2 * j + 1], ah, blf[2], blf[3]);
            }
        }

        // ---- scale + causal mask + row max ----
        const int k0 = kt * 64;
        const bool dm = (kt >= 2 * qt);
        float mx0 = -1e30f, mx1 = -1e30f;
#pragma unroll
        for (int t = 0; t < 8; t++) {
            int c0 = k0 + t * 8 + (lane & 3) * 2;
            s[t][0] *= scale; s[t][1] *= scale; s[t][2] *= scale; s[t][3] *= scale;
            if (dm) {
                if (c0     > r0g) s[t][0] = -1e30f;
                if (c0 + 1 > r0g) s[t][1] = -1e30f;
                if (c0     > r1g) s[t][2] = -1e30f;
                if (c0 + 1 > r1g) s[t][3] = -1e30f;
            }
            mx0 = fmaxf(mx0, fmaxf(s[t][0], s[t][1]));
            mx1 = fmaxf(mx1, fmaxf(s[t][2], s[t][3]));
        }
        mx0 = fmaxf(mx0, __shfl_xor_sync(0xffffffffu, mx0, 1));
        mx0 = fmaxf(mx0, __shfl_xor_sync(0xffffffffu, mx0, 2));
        mx1 = fmaxf(mx1, __shfl_xor_sync(0xffffffffu, mx1, 1));
        mx1 = fmaxf(mx1, __shfl_xor_sync(0xffffffffu, mx1, 2));

        float mn0 = fmaxf(m0, mx0), mn1 = fmaxf(m1, mx1);
        float a0 = __expf(m0 - mn0), a1 = __expf(m1 - mn1);
        m0 = mn0; m1 = mn1;

        // ---- P = exp(S - m); split to bf16 hi/lo in smem ----
        float rs0 = 0.f, rs1 = 0.f;
#pragma unroll
        for (int t = 0; t < 8; t++) {
            float p0 = __expf(s[t][0] - m0);
            float p1 = __expf(s[t][1] - m0);
            float p2 = __expf(s[t][2] - m1);
            float p3 = __expf(s[t][3] - m1);
            rs0 += p0 + p1; rs1 += p2 + p3;
            __nv_bfloat16 h0 = __float2bfloat16(p0), h1 = __float2bfloat16(p1);
            __nv_bfloat16 h2 = __float2bfloat16(p2), h3 = __float2bfloat16(p3);
            __nv_bfloat162 hp01 = {h0, h1}, hp23 = {h2, h3};
            __nv_bfloat162 lp01 = {__float2bfloat16(p0 - __bfloat162float(h0)),
                                   __float2bfloat16(p1 - __bfloat162float(h1))};
            __nv_bfloat162 lp23 = {__float2bfloat16(p2 - __bfloat162float(h2)),
                                   __float2bfloat16(p3 - __bfloat162float(h3))};
            uint32_t o0 = (uint32_t)(pr0 * 128 + (((t) ^ (pr0 & 7)) << 4) + (lane & 3) * 4);
            uint32_t o1 = (uint32_t)(pr1 * 128 + (((t) ^ (pr1 & 7)) << 4) + (lane & 3) * 4);
            *reinterpret_cast<__nv_bfloat162*>(smem + FA_PHI + o0) = hp01;
            *reinterpret_cast<__nv_bfloat162*>(smem + FA_PHI + o1) = hp23;
            *reinterpret_cast<__nv_bfloat162*>(smem + FA_PLO + o0) = lp01;
            *reinterpret_cast<__nv_bfloat162*>(smem + FA_PLO + o1) = lp23;
        }
        rs0 += __shfl_xor_sync(0xffffffffu, rs0, 1);
        rs0 += __shfl_xor_sync(0xffffffffu, rs0, 2);
        rs1 += __shfl_xor_sync(0xffffffffu, rs1, 1);
        rs1 += __shfl_xor_sync(0xffffffffu, rs1, 2);
        l0 = l0 * a0 + rs0;
        l1 = l1 * a1 + rs1;

        // rescale O
#pragma unroll
        for (int g = 0; g < 16; g++) {
            o[g][0] *= a0; o[g][1] *= a0; o[g][2] *= a1; o[g][3] *= a1;
        }
        __syncwarp();

        // ---- O += ph*vh + pl*vh + ph*vl ----
        const int vrow0 = (lane & 7) + ((asel & 1) << 3);
        const int vkc   = asel >> 1;
#pragma unroll
        for (int ks = 0; ks < 4; ++ks) {
            uint32_t ph[4], pl[4];
            ldmatrix_x4(ph, su + FA_PHI + SW128(qrow_s, ks * 2 + akc));
            ldmatrix_x4(pl, su + FA_PLO + SW128(qrow_s, ks * 2 + akc));
            int vr = ks * 16 + vrow0;
#pragma unroll
            for (int g = 0; g < 8; ++g) {
                uint32_t vf[4], vg[4];
                ldmatrix_x4_trans(vf, vbH + SW256(vr, g * 2 + vkc));
                ldmatrix_x4_trans(vg, vbL + SW256(vr, g * 2 + vkc));
                mma_bf16(o[2 * g],     ph, vf[0], vf[1]);
                mma_bf16(o[2 * g + 1], ph, vf[2], vf[3]);
                mma_bf16(o[2 * g],     pl, vf[0], vf[1]);
                mma_bf16(o[2 * g + 1], pl, vf[2], vf[3]);
                mma_bf16(o[2 * g],     ph, vg[0], vg[1]);
                mma_bf16(o[2 * g + 1], ph, vg[2], vg[3]);
            }
        }
        __syncthreads();
    }

    // ---- epilogue: y = O / l, split bf16 into x2 [row][hi(0..2047) | lo(2048..4095)] ----
    float inv0 = 1.0f / l0, inv1 = 1.0f / l1;
    int row0 = b * SEQ + q0 + wid * 16 + (lane >> 2);
    int row1 = row0 + 8;
#pragma unroll
    for (int g = 0; g < 16; g++) {
        int col = h * HDIM + g * 8 + (lane & 3) * 2;
        float y0 = o[g][0] * inv0, y1 = o[g][1] * inv0;
        float y2 = o[g][2] * inv1, y3 = o[g][3] * inv1;
        __nv_bfloat16 h0 = __float2bfloat16(y0), h1 = __float2bfloat16(y1);
        __nv_bfloat16 h2 = __float2bfloat16(y2), h3 = __float2bfloat16(y3);
        __nv_bfloat162 hi01 = {h0, h1}, hi23 = {h2, h3};
        __nv_bfloat162 lo01 = {__float2bfloat16(y0 - __bfloat162float(h0)),
                               __float2bfloat16(y1 - __bfloat162float(h1))};
        __nv_bfloat162 lo23 = {__float2bfloat16(y2 - __bfloat162float(h2)),
                               __float2bfloat16(y3 - __bfloat162float(h3))};
        *reinterpret_cast<__nv_bfloat162*>(x2 + (size_t)row0 * 4096 + col)        = hi01;
        *reinterpret_cast<__nv_bfloat162*>(x2 + (size_t)row0 * 4096 + 2048 + col) = lo01;
        *reinterpret_cast<__nv_bfloat162*>(x2 + (size_t)row1 * 4096 + col)        = hi23;
        *reinterpret_cast<__nv_bfloat162*>(x2 + (size_t)row1 * 4096 + 2048 + col) = lo23;
    }
}

// ---------------------------------------------------------------------------
// Launch
// ---------------------------------------------------------------------------
extern "C" void kernel_launch(void* const* d_in, const int* in_sizes, int n_in,
                              void* d_out, int out_size)
{
    const float* x    = (const float*)d_in[0];
    const float* cosp = (const float*)d_in[1];
    const float* sinp = (const float*)d_in[2];
    const float* Wq   = (const float*)d_in[3];
    const float* Wk   = (const float*)d_in[4];
    const float* Wv   = (const float*)d_in[5];
    const float* Wo   = (const float*)d_in[6];
    const float* bo   = (const float*)d_in[7];
    float* out = (float*)d_out;

    float *qs, *ks, *vs;
    __nv_bfloat16 *x2, *wq2, *wk2, *wv2, *wo2, *qh, *ql, *kh, *kl, *vh, *vl;
    cudaGetSymbolAddress((void**)&qs,  g_q);
    cudaGetSymbolAddress((void**)&ks,  g_k);
    cudaGetSymbolAddress((void**)&vs,  g_v);
    cudaGetSymbolAddress((void**)&x2,  g_x2);
    cudaGetSymbolAddress((void**)&wq2, g_wq2);
    cudaGetSymbolAddress((void**)&wk2, g_wk2);
    cudaGetSymbolAddress((void**)&wv2, g_wv2);
    cudaGetSymbolAddress((void**)&wo2, g_wo2);
    cudaGetSymbolAddress((void**)&qh,  g_qh);
    cudaGetSymbolAddress((void**)&ql,  g_ql);
    cudaGetSymbolAddress((void**)&kh,  g_kh);
    cudaGetSymbolAddress((void**)&kl,  g_kl);
    cudaGetSymbolAddress((void**)&vh,  g_vh);
    cudaGetSymbolAddress((void**)&vl,  g_vl);

    cudaFuncSetAttribute(hgemm_kernel, cudaFuncAttributeMaxDynamicSharedMemorySize, HG_SMEM);
    cudaFuncSetAttribute(flash_hmma_kernel, cudaFuncAttributeMaxDynamicSharedMemorySize, FA_SMEM);

    // input splits
    split2048_kernel<<<MROWS * CDIM / 4 / 256, 256>>>(x, x2);
    tsplit2048_kernel<<<dim3(QW / 32, CDIM / 32), dim3(32, 8)>>>(Wq, wq2, QW);
    tsplit2048_kernel<<<dim3(KW / 32, CDIM / 32), dim3(32, 8)>>>(Wk, wk2, KW);
    tsplit2048_kernel<<<dim3(KW / 32, CDIM / 32), dim3(32, 8)>>>(Wv, wv2, KW);
    tsplit2048_kernel<<<dim3(QW / 32, CDIM / 32), dim3(32, 8)>>>(Wo, wo2, QW);

    // QKV projections (HMMA)
    hgemm_kernel<<<dim3(QW / 128, MROWS / 128), 256, HG_SMEM>>>(x2, wq2, qs, QW, nullptr);
    hgemm_kernel<<<dim3(KW / 128, MROWS / 128), 256, HG_SMEM>>>(x2, wk2, ks, KW, nullptr);
    hgemm_kernel<<<dim3(KW / 128, MROWS / 128), 256, HG_SMEM>>>(x2, wv2, vs, KW, nullptr);

    // RMSNorm + RoPE -> bf16 splits; V -> bf16 hi/lo
    norm_rope_split_kernel<<<MROWS * (NHEAD + NKV), 128>>>(qs, ks, cosp, sinp, qh, ql, kh, kl);
    vsplit_kernel<<<MROWS * KW / 4 / 256, 256>>>(vs, vh, vl);

    // HMMA flash attention (writes split output into x2)
    dim3 ga(SEQ / 128, BATCH * NHEAD);
    flash_hmma_kernel<<<ga, 256, FA_SMEM>>>(qh, ql, kh, kl, vh, vl, x2);

    // output projection + bias
    hgemm_kernel<<<dim3(QW / 128, MROWS / 128), 256, HG_SMEM>>>(x2, wo2, out, QW, bo);
}